// round 7
// baseline (speedup 1.0000x reference)
#include <cuda_runtime.h>
#include <cuda_bf16.h>
#include <cstdint>

// ---------------- problem constants ----------------
#define B_    8
#define HQ_   32
#define TQ_   128
#define D_    128
#define HKV_  8
#define MAXB_ 64
#define BS_   128
#define NB_   32
#define CH_   64
#define SC_   0.08838834764831845f
#define EBIAS 20.0f

// ---------------- smem layout (bytes) ----------------
#define TMEMP_OFF  0
#define KFULL_OFF  16    // 2 mbarriers (stage 0/1)
#define KEMPTY_OFF 32    // 2 mbarriers
#define MBARS_OFF  48
#define QHI_OFF   1024
#define QLO_OFF   (QHI_OFF  + 32768)
#define KHI_OFF   (QLO_OFF  + 32768)   // 2 stages x 16KB
#define KLO_OFF   (KHI_OFF  + 32768)
#define VTHI_OFF  (KLO_OFF  + 32768)
#define VTLO_OFF  (VTHI_OFF + 32768)
#define PHI_OFF   (VTLO_OFF + 32768)
#define PLO_OFF   (PHI_OFF  + 16384)
#define SMEM_SZ   (PLO_OFF  + 16384)   // 230400 B

// TMEM columns
#define TMEM_S 0
#define TMEM_O 128
#define TMEM_NCOLS 256

// idesc kind::f16 bf16: dtype F32, atype/btype BF16, N/8<<17, M/16<<24
#define IDESC_S  ((1u<<4) | (1u<<7) | (1u<<10) | (8u<<17)  | (8u<<24))   // M128 N64
#define IDESC_PV ((1u<<4) | (1u<<7) | (1u<<10) | (16u<<17) | (8u<<24))   // M128 N128

#if defined(__CUDA_ARCH_FEAT_SM103_ALL) || defined(__CUDA_ARCH_FEAT_SM100_ALL) || !defined(__CUDA_ARCH__)
#define HAS_TC 1
#else
#define HAS_TC 0
#endif

#if HAS_TC
static __device__ __forceinline__ uint32_t smem_u32(const void* p){
    uint32_t a;
    asm("{ .reg .u64 t; cvta.to.shared.u64 t, %1; cvt.u32.u64 %0, t; }" : "=r"(a) : "l"(p));
    return a;
}
static __device__ __forceinline__ uint32_t elect_one(){
    uint32_t p;
    asm volatile("{ .reg .pred p; elect.sync _|p, 0xFFFFFFFF; selp.b32 %0,1,0,p; }" : "=r"(p));
    return p;
}

#define TCGEN05_ALLOC(sa, n) \
    asm volatile("tcgen05.alloc.cta_group::1.sync.aligned.shared::cta.b32 [%0], %1;" \
                 :: "r"((uint32_t)(sa)), "r"((uint32_t)(n)) : "memory")
#define TCGEN05_DEALLOC(t, n) \
    asm volatile("tcgen05.dealloc.cta_group::1.sync.aligned.b32 %0, %1;" :: "r"(t), "r"((uint32_t)(n)))
#define TCGEN05_RELINQ() \
    asm volatile("tcgen05.relinquish_alloc_permit.cta_group::1.sync.aligned;")
#define TCGEN05_COMMIT(mb) \
    asm volatile("tcgen05.commit.cta_group::1.mbarrier::arrive::one.shared::cluster.b64 [%0];" \
                 :: "r"((uint32_t)(mb)) : "memory")
#define TCGEN05_WAIT_LD()  asm volatile("tcgen05.wait::ld.sync.aligned;" ::: "memory")
#define TCGEN05_FENCE_BEFORE() asm volatile("tcgen05.fence::before_thread_sync;" ::: "memory")
#define TCGEN05_FENCE_AFTER()  asm volatile("tcgen05.fence::after_thread_sync;" ::: "memory")
#define FENCE_ASYNC_SHARED() asm volatile("fence.proxy.async.shared::cta;" ::: "memory")

#define MBARRIER_INIT(mb, n) \
    asm volatile("mbarrier.init.shared.b64 [%0], %1;" :: "r"((uint32_t)(mb)), "r"((uint32_t)(n)) : "memory")
#define MBARRIER_ARRIVE(mb) \
    asm volatile("mbarrier.arrive.shared.b64 _, [%0];" :: "r"((uint32_t)(mb)) : "memory")

#define MBARRIER_WAIT_PARITY(mb, ph) do { \
    uint32_t _m = (uint32_t)(mb); uint32_t _p = (uint32_t)(ph); uint32_t _d; \
    asm volatile("{ .reg .pred p; mbarrier.try_wait.parity.acquire.cta.shared::cta.b64 p, [%1], %2; selp.b32 %0,1,0,p; }" \
                 : "=r"(_d) : "r"(_m), "r"(_p) : "memory"); \
    if (!_d) { \
        asm volatile("{ .reg .pred P1; WL_%=: mbarrier.try_wait.parity.acquire.cta.shared::cta.b64 P1, [%0], %1, 0x989680; @P1 bra.uni WD_%=; bra.uni WL_%=; WD_%=: }" \
                     :: "r"(_m), "r"(_p) : "memory"); \
    } \
} while(0)

#define TCGEN05_LD_X32(r, ta) \
    asm volatile("tcgen05.ld.sync.aligned.32x32b.x32.b32 " \
        "{%0,%1,%2,%3,%4,%5,%6,%7,%8,%9,%10,%11,%12,%13,%14,%15," \
        "%16,%17,%18,%19,%20,%21,%22,%23,%24,%25,%26,%27,%28,%29,%30,%31}, [%32];" \
        : "=r"((r)[0]),"=r"((r)[1]),"=r"((r)[2]),"=r"((r)[3]),"=r"((r)[4]),"=r"((r)[5]),"=r"((r)[6]),"=r"((r)[7]), \
          "=r"((r)[8]),"=r"((r)[9]),"=r"((r)[10]),"=r"((r)[11]),"=r"((r)[12]),"=r"((r)[13]),"=r"((r)[14]),"=r"((r)[15]), \
          "=r"((r)[16]),"=r"((r)[17]),"=r"((r)[18]),"=r"((r)[19]),"=r"((r)[20]),"=r"((r)[21]),"=r"((r)[22]),"=r"((r)[23]), \
          "=r"((r)[24]),"=r"((r)[25]),"=r"((r)[26]),"=r"((r)[27]),"=r"((r)[28]),"=r"((r)[29]),"=r"((r)[30]),"=r"((r)[31]) \
        : "r"(ta))

static constexpr uint64_t DESC_BASE_SW128 =
    (2ull << 61) | (1ull << 46) | (64ull << 32) | (1ull << 16);
static __device__ __forceinline__ uint64_t mk_desc(uint32_t addr){
    return DESC_BASE_SW128 | ((uint64_t)(addr >> 4) & 0x3FFF);
}
static __device__ __forceinline__ void mma_bf16(uint32_t d, uint64_t ad, uint64_t bd,
                                                uint32_t idesc, bool acc){
    uint32_t e = acc ? 1u : 0u, z = 0u;
    asm volatile("{ .reg .pred p; setp.ne.u32 p, %5, 0;\n\t"
        "tcgen05.mma.cta_group::1.kind::f16 [%0], %1, %2, %3, {%4,%4,%4,%4}, p; }"
        :: "r"(d), "l"(ad), "l"(bd), "r"(idesc), "r"(z), "r"(e) : "memory");
}

// bf16 K-major SW128 blocked byte offset; natr = rows/8 atom-rows per 64-col block
static __device__ __forceinline__ uint32_t blkb(int r, int c, int natr){
    uint32_t b = (uint32_t)(((r >> 3) + (c >> 6) * natr) * 1024 + (r & 7) * 128 + (c & 63) * 2);
    return b ^ ((b >> 3) & 0x70);
}

// split 4 f32 into packed bf16 hi / lo residual pairs
static __device__ __forceinline__ void split4(float x0, float x1, float x2, float x3,
                                              uint2& hi, uint2& lo){
    uint32_t h01, h23, l01, l23;
    asm("cvt.rn.bf16x2.f32 %0, %1, %2;" : "=r"(h01) : "f"(x1), "f"(x0));
    asm("cvt.rn.bf16x2.f32 %0, %1, %2;" : "=r"(h23) : "f"(x3), "f"(x2));
    float r0 = x0 - __uint_as_float(h01 << 16);
    float r1 = x1 - __uint_as_float(h01 & 0xffff0000u);
    float r2 = x2 - __uint_as_float(h23 << 16);
    float r3 = x3 - __uint_as_float(h23 & 0xffff0000u);
    asm("cvt.rn.bf16x2.f32 %0, %1, %2;" : "=r"(l01) : "f"(r1), "f"(r0));
    asm("cvt.rn.bf16x2.f32 %0, %1, %2;" : "=r"(l23) : "f"(r3), "f"(r2));
    hi = make_uint2(h01, h23);
    lo = make_uint2(l01, l23);
}
#endif // HAS_TC

// ---------------- kernel ----------------
__global__ void __launch_bounds__(256, 1)
paged_attn_tc(const float* __restrict__ q,
              const float* __restrict__ sk,
              const float* __restrict__ sv,
              const int*   __restrict__ btab,
              const int*   __restrict__ ctxp,
              float*       __restrict__ out)
{
#if HAS_TC
    extern __shared__ char smc[];
    const uint32_t sb = smem_u32(smc);

    const int h = blockIdx.x;
    const int b = blockIdx.y;
    const int hkv = h >> 2;

    const int tid  = threadIdx.x;
    const int wid  = tid >> 5;
    const int lane = tid & 31;

    const int ctx = ctxp[b];
    const int nch = (ctx + CH_ - 1) >> 6;

    if (wid == 0) TCGEN05_ALLOC(sb + TMEMP_OFF, TMEM_NCOLS);
    if (tid == 0) {
        MBARRIER_INIT(sb + KFULL_OFF + 0, 1);
        MBARRIER_INIT(sb + KFULL_OFF + 8, 1);
        MBARRIER_INIT(sb + KEMPTY_OFF + 0, 1);
        MBARRIER_INIT(sb + KEMPTY_OFF + 8, 1);
        MBARRIER_INIT(sb + MBARS_OFF, 1);
    }
    __syncthreads();
    uint32_t tb;
    asm volatile("ld.shared.b32 %0, [%1];" : "=r"(tb) : "r"(sb + TMEMP_OFF));

    float* outb = out + ((size_t)(b * HQ_ + h) * TQ_) * D_;

    if (nch > 0) {
        // ---- all warps: load + split Q (128x128) ----
        const float* qb = q + ((size_t)(b * HQ_ + h) * TQ_) * D_;
        #pragma unroll
        for (int i = 0; i < 16; i++) {
            int idx = tid + i * 256;
            int r = idx >> 5, c4 = idx & 31;
            float4 v = *(const float4*)(qb + r * D_ + c4 * 4);
            uint2 hi, lo;
            split4(v.x, v.y, v.z, v.w, hi, lo);
            uint32_t off = blkb(r, c4 * 4, 16);
            *(uint2*)(smc + QHI_OFF + off) = hi;
            *(uint2*)(smc + QLO_OFF + off) = lo;
        }
        FENCE_ASYNC_SHARED();
        __syncthreads();

        if (wid >= 4) {
            // =========== PRODUCER: warps 4-7 ===========
            const int ptid = tid - 128;
            const int pwid = wid - 4;
            const int vr = lane >> 3, vc = lane & 7;
            for (int cc = 0; cc < nch; cc++) {
                const int s = cc & 1, u = cc >> 1;
                // wait stage free (PV of chunk cc-2 complete); first 2 pass
                MBARRIER_WAIT_PARITY(sb + KEMPTY_OFF + s * 8, (u + 1) & 1);

                const int page = btab[b * NB_ + (cc >> 1)];
                const float* kb = sk + (((size_t)(b * HKV_ + hkv) * MAXB_ + page) * BS_ + (size_t)(cc & 1) * CH_) * D_;
                const float* vb = sv + (((size_t)(b * HKV_ + hkv) * MAXB_ + page) * BS_ + (size_t)(cc & 1) * CH_) * D_;

                // K chunk 64x128 -> split bf16 (natr=8), stage s
                #pragma unroll
                for (int i = 0; i < 16; i++) {
                    int idx = ptid + i * 128;
                    int r = idx >> 5, c4 = idx & 31;
                    float4 v = *(const float4*)(kb + r * D_ + c4 * 4);
                    uint2 hi, lo;
                    split4(v.x, v.y, v.z, v.w, hi, lo);
                    uint32_t off = blkb(r, c4 * 4, 8) + s * 16384;
                    *(uint2*)(smc + KHI_OFF + off) = hi;
                    *(uint2*)(smc + KLO_OFF + off) = lo;
                }
                // V chunk: shuffle-transpose -> Vt [128 d, 64 l], split bf16 (natr=16)
                #pragma unroll
                for (int it = 0; it < 16; it++) {
                    int g = pwid * 16 + it;        // 0..63
                    int lb = g & 15, db = g >> 4;
                    int l0 = lb * 4, d0 = db * 32;
                    float4 f = *(const float4*)(vb + (l0 + vr) * D_ + d0 + vc * 4);
                    float o[4];
                    #pragma unroll
                    for (int j = 0; j < 4; j++) {
                        int src = j * 8 + vc;
                        float fx = __shfl_sync(0xffffffffu, f.x, src);
                        float fy = __shfl_sync(0xffffffffu, f.y, src);
                        float fz = __shfl_sync(0xffffffffu, f.z, src);
                        float fw = __shfl_sync(0xffffffffu, f.w, src);
                        o[j] = (vr == 0) ? fx : (vr == 1) ? fy : (vr == 2) ? fz : fw;
                    }
                    int d = d0 + vc * 4 + vr;
                    uint2 hi, lo;
                    split4(o[0], o[1], o[2], o[3], hi, lo);
                    uint32_t off = blkb(d, l0, 16) + s * 16384;
                    *(uint2*)(smc + VTHI_OFF + off) = hi;
                    *(uint2*)(smc + VTLO_OFF + off) = lo;
                }
                FENCE_ASYNC_SHARED();
                asm volatile("bar.sync 1, 128;" ::: "memory");
                if (tid == 128) MBARRIER_ARRIVE(sb + KFULL_OFF + s * 8);
            }
        } else {
            // =========== CONSUMER: warps 0-3 ===========
            float lsum = 0.f;
            const int row = wid * 32 + lane;
            for (int cc = 0; cc < nch; cc++) {
                const int s = cc & 1, u = cc >> 1;

                if (wid == 0) {
                    MBARRIER_WAIT_PARITY(sb + KFULL_OFF + s * 8, u & 1);
                    if (elect_one()) {
                        uint64_t qh = mk_desc(sb + QHI_OFF), ql = mk_desc(sb + QLO_OFF);
                        uint64_t kh = mk_desc(sb + KHI_OFF + s * 16384);
                        uint64_t kl = mk_desc(sb + KLO_OFF + s * 16384);
                        uint64_t at[3] = { qh, qh, ql };
                        uint64_t bt[3] = { kh, kl, kh };
                        #pragma unroll
                        for (int t = 0; t < 3; t++)
                            #pragma unroll
                            for (int kk = 0; kk < 8; kk++)
                                mma_bf16(tb + TMEM_S,
                                         at[t] + (kk >> 2) * 1024 + (kk & 3) * 2,
                                         bt[t] + (kk >> 2) * 512  + (kk & 3) * 2,
                                         IDESC_S, (t > 0) || (kk > 0));
                        TCGEN05_COMMIT(sb + MBARS_OFF);
                    }
                }
                // mbarS completion also implies PV(cc-1) done (commit covers priors)
                MBARRIER_WAIT_PARITY(sb + MBARS_OFF, cc & 1);
                TCGEN05_FENCE_AFTER();

                uint32_t sr[64];
                TCGEN05_LD_X32(sr, tb + TMEM_S);
                TCGEN05_LD_X32(sr + 32, tb + TMEM_S + 32);
                TCGEN05_WAIT_LD();
                #pragma unroll
                for (int c4 = 0; c4 < 16; c4++) {
                    float pc[4];
                    #pragma unroll
                    for (int j = 0; j < 4; j++) {
                        int c = c4 * 4 + j;
                        float sv_ = __uint_as_float(sr[c]);
                        float p = __expf(fmaf(sv_, SC_, -EBIAS));
                        p = (cc * CH_ + c < ctx) ? p : 0.f;
                        pc[j] = p;
                        lsum += p;
                    }
                    uint2 hi, lo;
                    split4(pc[0], pc[1], pc[2], pc[3], hi, lo);
                    uint32_t off = blkb(row, c4 * 4, 16);
                    *(uint2*)(smc + PHI_OFF + off) = hi;
                    *(uint2*)(smc + PLO_OFF + off) = lo;
                }
                TCGEN05_FENCE_BEFORE();
                FENCE_ASYNC_SHARED();
                asm volatile("bar.sync 2, 128;" ::: "memory");

                if (wid == 0 && elect_one()) {
                    uint64_t ph = mk_desc(sb + PHI_OFF), pl = mk_desc(sb + PLO_OFF);
                    uint64_t vh = mk_desc(sb + VTHI_OFF + s * 16384);
                    uint64_t vl = mk_desc(sb + VTLO_OFF + s * 16384);
                    uint64_t at[3] = { ph, ph, pl };
                    uint64_t bt[3] = { vh, vl, vh };
                    #pragma unroll
                    for (int t = 0; t < 3; t++)
                        #pragma unroll
                        for (int kk = 0; kk < 4; kk++)
                            mma_bf16(tb + TMEM_O,
                                     at[t] + kk * 2,
                                     bt[t] + kk * 2,
                                     IDESC_PV, (cc > 0) || (t > 0) || (kk > 0));
                    // commit frees stage s (K & Vt) and signals PV done
                    TCGEN05_COMMIT(sb + KEMPTY_OFF + s * 8);
                }
            }

            // ---- finalize: wait last PV, read O, divide ----
            {
                const int ls = (nch - 1) & 1, lu = (nch - 1) >> 1;
                MBARRIER_WAIT_PARITY(sb + KEMPTY_OFF + ls * 8, lu & 1);
            }
            TCGEN05_FENCE_AFTER();
            float inv = 1.f / fmaxf(lsum, 1e-9f);
            float* orow = outb + (size_t)row * D_;
            #pragma unroll
            for (int g = 0; g < 4; g++) {
                uint32_t orr[32];
                TCGEN05_LD_X32(orr, tb + TMEM_O + g * 32);
                TCGEN05_WAIT_LD();
                #pragma unroll
                for (int j4 = 0; j4 < 8; j4++) {
                    float4 o4 = make_float4(
                        __uint_as_float(orr[j4 * 4 + 0]) * inv,
                        __uint_as_float(orr[j4 * 4 + 1]) * inv,
                        __uint_as_float(orr[j4 * 4 + 2]) * inv,
                        __uint_as_float(orr[j4 * 4 + 3]) * inv);
                    *(float4*)(orow + g * 32 + j4 * 4) = o4;
                }
            }
            TCGEN05_FENCE_BEFORE();
        }
    } else {
        // ctx == 0: zero output tile
        #pragma unroll
        for (int i = 0; i < 16; i++) {
            int idx = tid + i * 256;
            int r = idx >> 5, c4 = idx & 31;
            *(float4*)(outb + (size_t)r * D_ + c4 * 4) = make_float4(0.f, 0.f, 0.f, 0.f);
        }
    }

    __syncthreads();
    if (wid == 0) {
        TCGEN05_RELINQ();
        TCGEN05_DEALLOC(tb, TMEM_NCOLS);
    }
#endif // HAS_TC
}

extern "C" void kernel_launch(void* const* d_in, const int* in_sizes, int n_in,
                              void* d_out, int out_size)
{
    const float* q  = (const float*)d_in[0];
    const float* sk = (const float*)d_in[1];
    const float* sv = (const float*)d_in[2];
    const int* btab = (const int*)d_in[3];
    const int* ctxp = (const int*)d_in[4];
    float* out = (float*)d_out;

    cudaFuncSetAttribute(paged_attn_tc,
                         cudaFuncAttributeMaxDynamicSharedMemorySize, SMEM_SZ);
    dim3 grid(HQ_, B_);
    paged_attn_tc<<<grid, 256, SMEM_SZ>>>(q, sk, sv, btab, ctxp, out);
}

// round 12
// speedup vs baseline: 1.5824x; 1.5824x over previous
#include <cuda_runtime.h>
#include <cuda_bf16.h>
#include <cstdint>

// ---------------- problem constants ----------------
#define B_    8
#define HQ_   32
#define TQ_   128
#define D_    128
#define HKV_  8
#define MAXB_ 64
#define BS_   128
#define NB_   32
#define CH_   64
#define SC2_  0.12751751134424653f   // D^-0.5 * log2(e)
#define EB2_  28.853900817779268f    // 20 * log2(e)

// ---------------- smem layout (bytes) ----------------
#define TMEMP_OFF  0
#define MBARS_OFF  16   // 2 ping-pong barriers for S commits
#define MBARPV_OFF 32
#define QHI_OFF   1024
#define QLO_OFF   (QHI_OFF + 32768)
#define KHI_OFF   (QLO_OFF + 32768)   // 2 stages x 16KB
#define KLO_OFF   (KHI_OFF + 32768)
#define VTHI_OFF  (KLO_OFF + 32768)   // Vt K-major [128 d, 64 l], 2 stages x 16KB
#define VTLO_OFF  (VTHI_OFF + 32768)
#define PHI_OFF   (VTLO_OFF + 32768)
#define PLO_OFF   (PHI_OFF + 16384)
#define SMEM_SZ   (PLO_OFF + 16384)   // 230400 B

// TMEM columns: S ping-pong at 0/64, O accum at 128..255
#define TMEM_O 128
#define TMEM_NCOLS 256

// idesc kind::f16 bf16: dtype F32(1<<4), atype BF16(1<<7), btype BF16(1<<10),
// N/8<<17, M/16<<24   (all K-major: PROVEN in round 6)
#define IDESC_S  ((1u<<4) | (1u<<7) | (1u<<10) | (8u<<17)  | (8u<<24))   // M128 N64
#define IDESC_PV ((1u<<4) | (1u<<7) | (1u<<10) | (16u<<17) | (8u<<24))   // M128 N128

#if defined(__CUDA_ARCH_FEAT_SM103_ALL) || defined(__CUDA_ARCH_FEAT_SM100_ALL) || !defined(__CUDA_ARCH__)
#define HAS_TC 1
#else
#define HAS_TC 0
#endif

#if HAS_TC
static __device__ __forceinline__ uint32_t smem_u32(const void* p){
    uint32_t a;
    asm("{ .reg .u64 t; cvta.to.shared.u64 t, %1; cvt.u32.u64 %0, t; }" : "=r"(a) : "l"(p));
    return a;
}
static __device__ __forceinline__ uint32_t elect_one(){
    uint32_t p;
    asm volatile("{ .reg .pred p; elect.sync _|p, 0xFFFFFFFF; selp.b32 %0,1,0,p; }" : "=r"(p));
    return p;
}

#define TCGEN05_ALLOC(sa, n) \
    asm volatile("tcgen05.alloc.cta_group::1.sync.aligned.shared::cta.b32 [%0], %1;" \
                 :: "r"((uint32_t)(sa)), "r"((uint32_t)(n)) : "memory")
#define TCGEN05_DEALLOC(t, n) \
    asm volatile("tcgen05.dealloc.cta_group::1.sync.aligned.b32 %0, %1;" :: "r"(t), "r"((uint32_t)(n)))
#define TCGEN05_RELINQ() \
    asm volatile("tcgen05.relinquish_alloc_permit.cta_group::1.sync.aligned;")
#define TCGEN05_COMMIT(mb) \
    asm volatile("tcgen05.commit.cta_group::1.mbarrier::arrive::one.shared::cluster.b64 [%0];" \
                 :: "r"((uint32_t)(mb)) : "memory")
#define TCGEN05_WAIT_LD()  asm volatile("tcgen05.wait::ld.sync.aligned;" ::: "memory")
#define TCGEN05_FENCE_BEFORE() asm volatile("tcgen05.fence::before_thread_sync;" ::: "memory")
#define TCGEN05_FENCE_AFTER()  asm volatile("tcgen05.fence::after_thread_sync;" ::: "memory")
#define FENCE_ASYNC_SHARED() asm volatile("fence.proxy.async.shared::cta;" ::: "memory")

#define MBARRIER_INIT(mb, n) \
    asm volatile("mbarrier.init.shared.b64 [%0], %1;" :: "r"((uint32_t)(mb)), "r"((uint32_t)(n)) : "memory")

#define MBARRIER_WAIT_PARITY(mb, ph) do { \
    uint32_t _m = (uint32_t)(mb); uint32_t _p = (uint32_t)(ph); uint32_t _d; \
    asm volatile("{ .reg .pred p; mbarrier.try_wait.parity.acquire.cta.shared::cta.b64 p, [%1], %2; selp.b32 %0,1,0,p; }" \
                 : "=r"(_d) : "r"(_m), "r"(_p) : "memory"); \
    if (!_d) { \
        asm volatile("{ .reg .pred P1; WL_%=: mbarrier.try_wait.parity.acquire.cta.shared::cta.b64 P1, [%0], %1, 0x989680; @P1 bra.uni WD_%=; bra.uni WL_%=; WD_%=: }" \
                     :: "r"(_m), "r"(_p) : "memory"); \
    } \
} while(0)

#define TCGEN05_LD_X32(r, ta) \
    asm volatile("tcgen05.ld.sync.aligned.32x32b.x32.b32 " \
        "{%0,%1,%2,%3,%4,%5,%6,%7,%8,%9,%10,%11,%12,%13,%14,%15," \
        "%16,%17,%18,%19,%20,%21,%22,%23,%24,%25,%26,%27,%28,%29,%30,%31}, [%32];" \
        : "=r"((r)[0]),"=r"((r)[1]),"=r"((r)[2]),"=r"((r)[3]),"=r"((r)[4]),"=r"((r)[5]),"=r"((r)[6]),"=r"((r)[7]), \
          "=r"((r)[8]),"=r"((r)[9]),"=r"((r)[10]),"=r"((r)[11]),"=r"((r)[12]),"=r"((r)[13]),"=r"((r)[14]),"=r"((r)[15]), \
          "=r"((r)[16]),"=r"((r)[17]),"=r"((r)[18]),"=r"((r)[19]),"=r"((r)[20]),"=r"((r)[21]),"=r"((r)[22]),"=r"((r)[23]), \
          "=r"((r)[24]),"=r"((r)[25]),"=r"((r)[26]),"=r"((r)[27]),"=r"((r)[28]),"=r"((r)[29]),"=r"((r)[30]),"=r"((r)[31]) \
        : "r"(ta))

// K-major SW128: LBO=1, SBO=64  (the only descriptor flavor we use — proven)
static constexpr uint64_t DESC_K =
    (2ull << 61) | (1ull << 46) | (64ull << 32) | (1ull << 16);
static __device__ __forceinline__ uint64_t mk_desc(uint32_t addr){
    return DESC_K | ((uint64_t)(addr >> 4) & 0x3FFF);
}
static __device__ __forceinline__ void mma_bf16(uint32_t d, uint64_t ad, uint64_t bd,
                                                uint32_t idesc, bool acc){
    uint32_t e = acc ? 1u : 0u, z = 0u;
    asm volatile("{ .reg .pred p; setp.ne.u32 p, %5, 0;\n\t"
        "tcgen05.mma.cta_group::1.kind::f16 [%0], %1, %2, %3, {%4,%4,%4,%4}, p; }"
        :: "r"(d), "l"(ad), "l"(bd), "r"(idesc), "r"(z), "r"(e) : "memory");
}

// bf16 K-major SW128 blocked byte offset; natr = rows/8 atom-rows per 64-col block
static __device__ __forceinline__ uint32_t blkb(int r, int c, int natr){
    uint32_t b = (uint32_t)(((r >> 3) + (c >> 6) * natr) * 1024 + (r & 7) * 128 + (c & 63) * 2);
    return b ^ ((b >> 3) & 0x70);
}

// split 4 f32 into packed bf16 hi / lo residual pairs
static __device__ __forceinline__ void split4(float x0, float x1, float x2, float x3,
                                              uint2& hi, uint2& lo){
    uint32_t h01, h23, l01, l23;
    asm("cvt.rn.bf16x2.f32 %0, %1, %2;" : "=r"(h01) : "f"(x1), "f"(x0));
    asm("cvt.rn.bf16x2.f32 %0, %1, %2;" : "=r"(h23) : "f"(x3), "f"(x2));
    float r0 = x0 - __uint_as_float(h01 << 16);
    float r1 = x1 - __uint_as_float(h01 & 0xffff0000u);
    float r2 = x2 - __uint_as_float(h23 << 16);
    float r3 = x3 - __uint_as_float(h23 & 0xffff0000u);
    asm("cvt.rn.bf16x2.f32 %0, %1, %2;" : "=r"(l01) : "f"(r1), "f"(r0));
    asm("cvt.rn.bf16x2.f32 %0, %1, %2;" : "=r"(l23) : "f"(r3), "f"(r2));
    hi = make_uint2(h01, h23);
    lo = make_uint2(l01, l23);
}
#endif // HAS_TC

// ---------------- kernel ----------------
__global__ void __launch_bounds__(256, 1)
paged_attn_tc(const float* __restrict__ q,
              const float* __restrict__ sk,
              const float* __restrict__ sv,
              const int*   __restrict__ btab,
              const int*   __restrict__ ctxp,
              float*       __restrict__ out)
{
#if HAS_TC
    extern __shared__ char smc[];
    const uint32_t sb = smem_u32(smc);

    const int h = blockIdx.x;
    const int b = blockIdx.y;
    const int hkv = h >> 2;

    const int tid  = threadIdx.x;
    const int wid  = tid >> 5;
    const int lane = tid & 31;
    const int half = wid >> 2;            // 0: S cols 0-31, 1: cols 32-63
    const int row  = (wid & 3) * 32 + lane;

    const int ctx = ctxp[b];
    const int nch = (ctx + CH_ - 1) >> 6;

    if (wid == 0) TCGEN05_ALLOC(sb + TMEMP_OFF, TMEM_NCOLS);
    if (tid == 0) {
        MBARRIER_INIT(sb + MBARS_OFF + 0, 1);
        MBARRIER_INIT(sb + MBARS_OFF + 8, 1);
        MBARRIER_INIT(sb + MBARPV_OFF, 1);
    }
    __syncthreads();
    uint32_t tb;
    asm volatile("ld.shared.b32 %0, [%1];" : "=r"(tb) : "r"(sb + TMEMP_OFF));

    float* outb = out + ((size_t)(b * HQ_ + h) * TQ_) * D_;
    const size_t kvhead = (size_t)(b * HKV_ + hkv) * MAXB_;
    const int vr = lane >> 3, vc = lane & 7;   // transpose lane coords

    if (nch > 0) {
        // ---- prologue: load+split Q (128x128) and K/Vt(0) into stage 0 ----
        const float* qb = q + ((size_t)(b * HQ_ + h) * TQ_) * D_;
        #pragma unroll
        for (int i = 0; i < 16; i++) {
            int idx = tid + i * 256;
            int r = idx >> 5, c4 = idx & 31;
            float4 v = *(const float4*)(qb + r * D_ + c4 * 4);
            uint2 hi, lo;
            split4(v.x, v.y, v.z, v.w, hi, lo);
            uint32_t off = blkb(r, c4 * 4, 16);
            *(uint2*)(smc + QHI_OFF + off) = hi;
            *(uint2*)(smc + QLO_OFF + off) = lo;
        }
        {
            const int page0 = btab[b * NB_];
            const float* kb = sk + (kvhead + page0) * (size_t)(BS_ * D_);
            const float* vb = sv + (kvhead + page0) * (size_t)(BS_ * D_);
            #pragma unroll
            for (int i = 0; i < 8; i++) {
                int idx = tid + i * 256;
                int r = idx >> 5, c4 = idx & 31;
                float4 v = *(const float4*)(kb + r * D_ + c4 * 4);
                uint2 hi, lo;
                split4(v.x, v.y, v.z, v.w, hi, lo);
                uint32_t off = blkb(r, c4 * 4, 8);
                *(uint2*)(smc + KHI_OFF + off) = hi;
                *(uint2*)(smc + KLO_OFF + off) = lo;
            }
            // Vt transpose (proven R6 path): g = wid*8+it over 64 groups
            #pragma unroll
            for (int it = 0; it < 8; it++) {
                int g = wid * 8 + it;
                int lb = g & 15, db = g >> 4;
                int l0 = lb * 4, d0 = db * 32;
                float4 f = *(const float4*)(vb + (l0 + vr) * D_ + d0 + vc * 4);
                float o[4];
                #pragma unroll
                for (int j = 0; j < 4; j++) {
                    int src = j * 8 + vc;
                    float fx = __shfl_sync(0xffffffffu, f.x, src);
                    float fy = __shfl_sync(0xffffffffu, f.y, src);
                    float fz = __shfl_sync(0xffffffffu, f.z, src);
                    float fw = __shfl_sync(0xffffffffu, f.w, src);
                    o[j] = (vr == 0) ? fx : (vr == 1) ? fy : (vr == 2) ? fz : fw;
                }
                int d = d0 + vc * 4 + vr;
                uint2 hi, lo;
                split4(o[0], o[1], o[2], o[3], hi, lo);
                uint32_t off = blkb(d, l0, 16);
                *(uint2*)(smc + VTHI_OFF + off) = hi;
                *(uint2*)(smc + VTLO_OFF + off) = lo;
            }
        }
        FENCE_ASYNC_SHARED();
        __syncthreads();

        // issue S(0) into TMEM cols 0-63
        if (wid == 0 && elect_one()) {
            uint64_t qh = mk_desc(sb + QHI_OFF), ql = mk_desc(sb + QLO_OFF);
            uint64_t kh = mk_desc(sb + KHI_OFF), kl = mk_desc(sb + KLO_OFF);
            uint64_t at[3] = { qh, qh, ql };
            uint64_t bt[3] = { kh, kl, kh };
            #pragma unroll
            for (int t = 0; t < 3; t++)
                #pragma unroll
                for (int kk = 0; kk < 8; kk++)
                    mma_bf16(tb, at[t] + (kk >> 2) * 1024 + (kk & 3) * 2,
                             bt[t] + (kk >> 2) * 512 + (kk & 3) * 2,
                             IDESC_S, (t > 0) || (kk > 0));
            TCGEN05_COMMIT(sb + MBARS_OFF);     // barrier 0 for even chunks
        }

        float lsum = 0.f;

        for (int cc = 0; cc < nch; cc++) {
            const int s = cc & 1;

            // wait PV(cc-1): frees stage s^1 (K & Vt) and the P buffer
            if (cc > 0) MBARRIER_WAIT_PARITY(sb + MBARPV_OFF, (cc - 1) & 1);

            // prefetch K/Vt(cc+1) into stage s^1; issue S(cc+1) (overlaps softmax)
            if (cc + 1 < nch) {
                const int nc = cc + 1;
                const int page = btab[b * NB_ + (nc >> 1)];
                const float* kb = sk + ((kvhead + page) * BS_ + (size_t)(nc & 1) * CH_) * D_;
                const float* vb = sv + ((kvhead + page) * BS_ + (size_t)(nc & 1) * CH_) * D_;
                const uint32_t stoff = (uint32_t)(s ^ 1) * 16384u;
                #pragma unroll
                for (int i = 0; i < 8; i++) {
                    int idx = tid + i * 256;
                    int r = idx >> 5, c4 = idx & 31;
                    float4 v = *(const float4*)(kb + r * D_ + c4 * 4);
                    uint2 hi, lo;
                    split4(v.x, v.y, v.z, v.w, hi, lo);
                    uint32_t off = blkb(r, c4 * 4, 8) + stoff;
                    *(uint2*)(smc + KHI_OFF + off) = hi;
                    *(uint2*)(smc + KLO_OFF + off) = lo;
                }
                #pragma unroll
                for (int it = 0; it < 8; it++) {
                    int g = wid * 8 + it;
                    int lb = g & 15, db = g >> 4;
                    int l0 = lb * 4, d0 = db * 32;
                    float4 f = *(const float4*)(vb + (l0 + vr) * D_ + d0 + vc * 4);
                    float o[4];
                    #pragma unroll
                    for (int j = 0; j < 4; j++) {
                        int src = j * 8 + vc;
                        float fx = __shfl_sync(0xffffffffu, f.x, src);
                        float fy = __shfl_sync(0xffffffffu, f.y, src);
                        float fz = __shfl_sync(0xffffffffu, f.z, src);
                        float fw = __shfl_sync(0xffffffffu, f.w, src);
                        o[j] = (vr == 0) ? fx : (vr == 1) ? fy : (vr == 2) ? fz : fw;
                    }
                    int d = d0 + vc * 4 + vr;
                    uint2 hi, lo;
                    split4(o[0], o[1], o[2], o[3], hi, lo);
                    uint32_t off = blkb(d, l0, 16) + stoff;
                    *(uint2*)(smc + VTHI_OFF + off) = hi;
                    *(uint2*)(smc + VTLO_OFF + off) = lo;
                }
                FENCE_ASYNC_SHARED();
                __syncthreads();
                if (wid == 0 && elect_one()) {
                    uint64_t qh = mk_desc(sb + QHI_OFF), ql = mk_desc(sb + QLO_OFF);
                    uint64_t kh = mk_desc(sb + KHI_OFF + stoff), kl = mk_desc(sb + KLO_OFF + stoff);
                    uint64_t at[3] = { qh, qh, ql };
                    uint64_t bt[3] = { kh, kl, kh };
                    #pragma unroll
                    for (int t = 0; t < 3; t++)
                        #pragma unroll
                        for (int kk = 0; kk < 8; kk++)
                            mma_bf16(tb + (uint32_t)(nc & 1) * 64,
                                     at[t] + (kk >> 2) * 1024 + (kk & 3) * 2,
                                     bt[t] + (kk >> 2) * 512 + (kk & 3) * 2,
                                     IDESC_S, (t > 0) || (kk > 0));
                    TCGEN05_COMMIT(sb + MBARS_OFF + (uint32_t)(nc & 1) * 8);
                }
            }

            // ---- wait S(cc), 8-warp softmax ----
            MBARRIER_WAIT_PARITY(sb + MBARS_OFF + (uint32_t)s * 8, (cc >> 1) & 1);
            TCGEN05_FENCE_AFTER();
            uint32_t sr[32];
            TCGEN05_LD_X32(sr, tb + (uint32_t)s * 64 + (uint32_t)half * 32);
            TCGEN05_WAIT_LD();
            const int cbase = cc * CH_ + half * 32;
            #pragma unroll
            for (int c4 = 0; c4 < 8; c4++) {
                float pc[4];
                #pragma unroll
                for (int j = 0; j < 4; j++) {
                    float sv_ = __uint_as_float(sr[c4 * 4 + j]);
                    float p = exp2f(fmaf(sv_, SC2_, -EB2_));
                    p = (cbase + c4 * 4 + j < ctx) ? p : 0.f;
                    pc[j] = p;
                    lsum += p;
                }
                uint2 hi, lo;
                split4(pc[0], pc[1], pc[2], pc[3], hi, lo);
                uint32_t off = blkb(row, half * 32 + c4 * 4, 16);
                *(uint2*)(smc + PHI_OFF + off) = hi;
                *(uint2*)(smc + PLO_OFF + off) = lo;
            }
            TCGEN05_FENCE_BEFORE();
            FENCE_ASYNC_SHARED();
            __syncthreads();

            // ---- PV: O += P @ Vt^T (M=128 N=128 K=64, all K-major; proven) ----
            if (wid == 0 && elect_one()) {
                const uint32_t stoff = (uint32_t)s * 16384u;
                uint64_t ph = mk_desc(sb + PHI_OFF), pl = mk_desc(sb + PLO_OFF);
                uint64_t vh = mk_desc(sb + VTHI_OFF + stoff);
                uint64_t vl = mk_desc(sb + VTLO_OFF + stoff);
                uint64_t at[3] = { ph, ph, pl };
                uint64_t bt[3] = { vh, vl, vh };
                #pragma unroll
                for (int t = 0; t < 3; t++)
                    #pragma unroll
                    for (int kk = 0; kk < 4; kk++)
                        mma_bf16(tb + TMEM_O,
                                 at[t] + kk * 2,
                                 bt[t] + kk * 2,
                                 IDESC_PV, (cc > 0) || (t > 0) || (kk > 0));
                TCGEN05_COMMIT(sb + MBARPV_OFF);
            }
        }

        // ---- finalize ----
        MBARRIER_WAIT_PARITY(sb + MBARPV_OFF, (nch - 1) & 1);
        TCGEN05_FENCE_AFTER();
        float* ls = (float*)(smc + PHI_OFF);    // P region free now
        ls[half * 128 + row] = lsum;
        __syncthreads();
        float inv = 1.f / fmaxf(ls[row] + ls[128 + row], 1e-9f);
        uint32_t orr[64];
        TCGEN05_LD_X32(orr, tb + TMEM_O + (uint32_t)half * 64);
        TCGEN05_LD_X32(orr + 32, tb + TMEM_O + (uint32_t)half * 64 + 32);
        TCGEN05_WAIT_LD();
        float* orow = outb + (size_t)row * D_ + half * 64;
        #pragma unroll
        for (int j4 = 0; j4 < 16; j4++) {
            float4 o4 = make_float4(
                __uint_as_float(orr[j4 * 4 + 0]) * inv,
                __uint_as_float(orr[j4 * 4 + 1]) * inv,
                __uint_as_float(orr[j4 * 4 + 2]) * inv,
                __uint_as_float(orr[j4 * 4 + 3]) * inv);
            *(float4*)(orow + j4 * 4) = o4;
        }
        TCGEN05_FENCE_BEFORE();
    } else {
        // ctx == 0: zero output tile
        #pragma unroll
        for (int i = 0; i < 16; i++) {
            int idx = tid + i * 256;
            int r = idx >> 5, c4 = idx & 31;
            *(float4*)(outb + (size_t)r * D_ + c4 * 4) = make_float4(0.f, 0.f, 0.f, 0.f);
        }
    }

    __syncthreads();
    if (wid == 0) {
        TCGEN05_RELINQ();
        TCGEN05_DEALLOC(tb, TMEM_NCOLS);
    }
#endif // HAS_TC
}

extern "C" void kernel_launch(void* const* d_in, const int* in_sizes, int n_in,
                              void* d_out, int out_size)
{
    const float* q  = (const float*)d_in[0];
    const float* sk = (const float*)d_in[1];
    const float* sv = (const float*)d_in[2];
    const int* btab = (const int*)d_in[3];
    const int* ctxp = (const int*)d_in[4];
    float* out = (float*)d_out;

    cudaFuncSetAttribute(paged_attn_tc,
                         cudaFuncAttributeMaxDynamicSharedMemorySize, SMEM_SZ);
    dim3 grid(HQ_, B_);
    paged_attn_tc<<<grid, 256, SMEM_SZ>>>(q, sk, sv, btab, ctxp, out);
}